// round 9
// baseline (speedup 1.0000x reference)
#include <cuda_runtime.h>
#include <cstdint>

// SINDy library: out[row] = [1, z(32), z_i*z_j (528), z_a*z_b*z_c (5984), sin(z)(32)]
// 8192 rows x 6577 cols fp32.
// R9: fully branchless 8-wide main loop. Boundary groups are REDIRECTED into a
// per-row precomputed fixup region in smem (pre-multiplied, za=1.0), so every
// group runs the identical uniform path: 2xLDS.128 + LDS.32 + 4x mul.f32x2 + 2xSTG.128.

#define NDIM     32
#define NPAIRS   528
#define NCOLS    6577
#define SBUF_PAD 600
#define NTHREADS 256
#define FIXBASE  (4 * SBUF_PAD)      // float index of fixup region in s_all
#define FIX_MAX  384                 // >= 8 * (#boundary groups per phase)
#define SALL_N   (FIXBASE + FIX_MAX) // 2784 floats
#define TB_PAD   1088                // >= max ng8 (822) + NTHREADS

static constexpr int pair_index(int i, int j) {
    return i * NDIM - (i * (i - 1)) / 2 + (j - i);
}

// ---- per-column (k, a) table: value = s_mul[a] * buf[k] (a=32 -> 1.0) ----
struct ColTbl { unsigned short e[NCOLS]; };
static constexpr ColTbl make_col_tbl() {
    ColTbl t{};
    for (int c = 0; c < 561; ++c)
        t.e[c] = (unsigned short)((unsigned)c | (32u << 10));
    {
        int col = 561;
        for (int a = 0; a < NDIM; ++a)
            for (int b = a; b < NDIM; ++b)
                for (int c = b; c < NDIM; ++c) {
                    unsigned k = 33u + (unsigned)pair_index(b, c);
                    t.e[col++] = (unsigned short)(k | ((unsigned)a << 10));
                }
    }
    for (int i = 0; i < NDIM; ++i)
        t.e[6545 + i] = (unsigned short)((unsigned)(561 + i) | (32u << 10));
    return t;
}
__device__ constexpr ColTbl G_COL = make_col_tbl();

// ---- per-column triple-factor decomposition into s_m3[66] = [z(32), 1, sin(32), pad] ----
// value(col) = s_m3[m0] * s_m3[m1] * s_m3[m2]; packed m0 | m1<<7 | m2<<14.
static constexpr unsigned col_m3(int c) {
    if (c == 0)   return 32u | (32u << 7) | (32u << 14);
    if (c < 33)   return (unsigned)(c - 1) | (32u << 7) | (32u << 14);
    if (c < 561) {                                // pairs
        int p = c - 33, i = 0;
        while (p >= NDIM - i) { p -= NDIM - i; ++i; }
        int j = i + p;
        return (unsigned)i | ((unsigned)j << 7) | (32u << 14);
    }
    if (c < 6545) {                               // triples
        int r = c - 561;
        int a = 0;
        while (true) {
            int m = NDIM - a, cnt = m * (m + 1) / 2;
            if (r < cnt) break;
            r -= cnt; ++a;
        }
        int b = a;
        while (r >= NDIM - b) { r -= NDIM - b; ++b; }
        int cc = b + r;
        return (unsigned)a | ((unsigned)b << 7) | ((unsigned)cc << 14);
    }
    return (unsigned)(33 + (c - 6545)) | (32u << 7) | (32u << 14);  // sin
}

// ---- 8-wide group table + fixup source list, per phase ----
struct Tbl8 {
    unsigned e[4][TB_PAD];   // low16: byte offset into s_all; bits[16..30): za byte offset
    unsigned fixsrc[4][FIX_MAX];  // packed m3 triple-factor source for fix slot i
    int      ng[4];
    int      nfix[4];
};

static constexpr Tbl8 make_tbl8() {
    ColTbl ct = make_col_tbl();
    Tbl8 t{};
    for (int ph = 0; ph < 4; ++ph) {
        int ng = (NCOLS - ph) / 8;
        t.ng[ph] = ng;
        int nf = 0;
        for (int g = 0; g < ng; ++g) {
            int c0 = ph + 8 * g;
            unsigned k0 = ct.e[c0] & 1023u;
            unsigned a0 = (unsigned)(ct.e[c0] >> 10);
            bool uniform = true;
            for (int j = 1; j < 8; ++j) {
                unsigned kj = ct.e[c0 + j] & 1023u;
                unsigned aj = (unsigned)(ct.e[c0 + j] >> 10);
                if (kj != k0 + (unsigned)j || aj != a0) { uniform = false; break; }
            }
            if (uniform) {
                unsigned P   = (4u - (k0 & 3u)) & 3u;
                unsigned off = (P * SBUF_PAD + k0 + P) * 4u;
                t.e[ph][g] = off | ((a0 * 4u) << 16);
            } else {
                // redirect into fixup region (pre-multiplied values, za = 1.0 at s_mul idx 32)
                unsigned off = (unsigned)(FIXBASE + nf) * 4u;
                t.e[ph][g] = off | ((32u * 4u) << 16);
                for (int j = 0; j < 8; ++j)
                    t.fixsrc[ph][nf++] = col_m3(c0 + j);
            }
        }
        t.nfix[ph] = nf;   // nf stays within FIX_MAX by construction (~280)
        for (int g = ng; g < TB_PAD; ++g) t.e[ph][g] = 0;
        for (int i = nf; i < FIX_MAX; ++i) t.fixsrc[ph][i] = 32u | (32u << 7) | (32u << 14);
    }
    return t;
}
__device__ constexpr Tbl8 G8 = make_tbl8();

struct PairTbl { unsigned short e[NPAIRS]; };
static constexpr PairTbl make_pair_tbl() {
    PairTbl t{};
    int p = 0;
    for (int i = 0; i < NDIM; ++i)
        for (int j = i; j < NDIM; ++j)
            t.e[p++] = (unsigned short)((unsigned)i | ((unsigned)j << 8));
    return t;
}
__device__ constexpr PairTbl G_PAIR = make_pair_tbl();

__device__ __forceinline__ void mul2(float& ox, float& oy,
                                     float ax, float ay, uint64_t b) {
    uint64_t a, r;
    asm("mov.b64 %0,{%1,%2};" : "=l"(a) : "f"(ax), "f"(ay));
    asm("mul.rn.f32x2 %0,%1,%2;" : "=l"(r) : "l"(a), "l"(b));
    asm("mov.b64 {%0,%1},%2;" : "=f"(ox), "=f"(oy) : "l"(r));
}

__global__ __launch_bounds__(NTHREADS) void sindy_library_kernel(
    const float* __restrict__ z, float* __restrict__ out)
{
    // s_all: 4 shifted s_buf copies (copy P at P*SBUF_PAD, s_copyP[P+k]=buf[k])
    // followed by the fixup region at FIXBASE (16B aligned: FIXBASE*4 = 9600).
    __shared__ __align__(16) float s_all[SALL_N];
    __shared__ float s_mul[NDIM + 1];   // z..., 1.0f at [32]
    __shared__ float s_m3[66];          // z(32), 1.0 at [32], sin at [33..64]

    const int row = blockIdx.x;
    const int t   = threadIdx.x;

    if (t < NDIM) {
        float v  = z[row * NDIM + t];
        float sv = __sinf(v);
        s_mul[t]      = v;
        s_m3[t]       = v;
        s_m3[33 + t]  = sv;
        #pragma unroll
        for (int P = 0; P < 4; ++P) {
            s_all[P * SBUF_PAD + P + 1 + t]   = v;
            s_all[P * SBUF_PAD + P + 561 + t] = sv;
        }
    } else if (t == NDIM) {
        s_mul[NDIM] = 1.0f;
        s_m3[32]    = 1.0f;
        #pragma unroll
        for (int P = 0; P < 4; ++P) s_all[P * SBUF_PAD + P] = 1.0f;
    }
    __syncthreads();

    const int ph = (4 - (row & 3)) & 3;

    // Pair products into all 4 shifted copies.
    for (int p = t; p < NPAIRS; p += NTHREADS) {
        unsigned ij = (unsigned)G_PAIR.e[p];
        float v = s_mul[ij & 31u] * s_mul[(ij >> 8) & 31u];
        #pragma unroll
        for (int P = 0; P < 4; ++P) s_all[P * SBUF_PAD + P + 33 + p] = v;
    }
    // Fixup values (pre-multiplied products of up to three s_m3 factors).
    {
        const int nfix = G8.nfix[ph];
        for (int f = t; f < nfix; f += NTHREADS) {
            unsigned s = __ldg(&G8.fixsrc[ph][f]);
            s_all[FIXBASE + f] =
                s_m3[s & 127u] * s_m3[(s >> 7) & 127u] * s_m3[(s >> 14) & 127u];
        }
    }
    __syncthreads();

    float* __restrict__ o = out + (size_t)row * NCOLS;

    // Head scalars (< 4 cols)
    if (t < ph) {
        unsigned e = (unsigned)G_COL.e[t];
        o[t] = s_mul[e >> 10] * s_all[e & 1023u];
    }

    const int ng = G8.ng[ph];
    const unsigned* __restrict__ tb = &G8.e[ph][0];
    const char* __restrict__ sc = (const char*)&s_all[0];
    const char* __restrict__ sm = (const char*)&s_mul[0];

    unsigned e = __ldg(&tb[t]);                   // prefetch first entry
    for (int g = t; g < ng; g += NTHREADS) {
        unsigned en = __ldg(&tb[g + NTHREADS]);   // padded: always in-bounds

        unsigned off = e & 0xFFFFu;
        float4 b0 = *(const float4*)(sc + off);
        float4 b1 = *(const float4*)(sc + off + 16);
        float  za = *(const float*)(sm + ((e >> 16) & 0x3FFFu));

        uint64_t zz;
        asm("mov.b64 %0,{%1,%1};" : "=l"(zz) : "f"(za));
        float4 r0, r1;
        mul2(r0.x, r0.y, b0.x, b0.y, zz);
        mul2(r0.z, r0.w, b0.z, b0.w, zz);
        mul2(r1.x, r1.y, b1.x, b1.y, zz);
        mul2(r1.z, r1.w, b1.z, b1.w, zz);

        float* po = o + ph + 8 * g;
        __stcs((float4*)po,       r0);
        __stcs((float4*)(po + 4), r1);
        e = en;
    }

    // Tail scalars (< 8 cols)
    {
        int c = ph + 8 * ng + t;
        if (c < NCOLS) {
            unsigned ee = (unsigned)G_COL.e[c];
            o[c] = s_mul[ee >> 10] * s_all[ee & 1023u];
        }
    }
}

extern "C" void kernel_launch(void* const* d_in, const int* in_sizes, int n_in,
                              void* d_out, int out_size) {
    const float* z   = (const float*)d_in[0];
    float*       out = (float*)d_out;
    sindy_library_kernel<<<8192, NTHREADS>>>(z, out);
}

// round 10
// speedup vs baseline: 1.3628x; 1.3628x over previous
#include <cuda_runtime.h>
#include <cstdint>

// SINDy library: out[row] = [1, z(32), z_i*z_j (528), z_a*z_b*z_c (5984), sin(z)(32)]
// 8192 rows x 6577 cols fp32.
// R10 = R7 memory shape (4-wide, ONE LDS.128 + ONE STG.128 per thread-iter) +
// branchless boundary handling: boundary groups redirect to a per-row
// precomputed, pre-multiplied fixup region in smem (za = 1.0). No divergence,
// no double writes, plain FMULs (low regs).

#define NDIM     32
#define NPAIRS   528
#define NCOLS    6577
#define SBUF_PAD 600
#define NTHREADS 256
#define FIXBASE  (4 * SBUF_PAD)       // float idx of fixup region; 9600 B -> 16B aligned
#define FIX_MAX  320                  // >= 4 * (#boundary groups per phase)
#define SALL_N   (FIXBASE + FIX_MAX)
#define TB_PAD   1920                 // >= max ng4 (1644) + NTHREADS

static constexpr int pair_index(int i, int j) {
    return i * NDIM - (i * (i - 1)) / 2 + (j - i);
}

// ---- per-column (k, a): value = s_mul[a] * buf[k]; a=32 -> 1.0 ----
struct ColTbl { unsigned short e[NCOLS]; };
static constexpr ColTbl make_col_tbl() {
    ColTbl t{};
    for (int c = 0; c < 561; ++c)
        t.e[c] = (unsigned short)((unsigned)c | (32u << 10));
    {
        int col = 561;
        for (int a = 0; a < NDIM; ++a)
            for (int b = a; b < NDIM; ++b)
                for (int c = b; c < NDIM; ++c) {
                    unsigned k = 33u + (unsigned)pair_index(b, c);
                    t.e[col++] = (unsigned short)(k | ((unsigned)a << 10));
                }
    }
    for (int i = 0; i < NDIM; ++i)
        t.e[6545 + i] = (unsigned short)((unsigned)(561 + i) | (32u << 10));
    return t;
}
__device__ constexpr ColTbl G_COL = make_col_tbl();

// ---- per-column decomposition into s_m3[65] = [z(32), 1.0, sin(32)] ----
// value(col) = s_m3[m0] * s_m3[m1] * s_m3[m2]; packed m0 | m1<<7 | m2<<14.
static constexpr unsigned col_m3(int c) {
    if (c == 0)   return 32u | (32u << 7) | (32u << 14);
    if (c < 33)   return (unsigned)(c - 1) | (32u << 7) | (32u << 14);
    if (c < 561) {
        int p = c - 33, i = 0;
        while (p >= NDIM - i) { p -= NDIM - i; ++i; }
        return (unsigned)i | ((unsigned)(i + p) << 7) | (32u << 14);
    }
    if (c < 6545) {
        int r = c - 561, a = 0;
        while (true) {
            int m = NDIM - a, cnt = m * (m + 1) / 2;
            if (r < cnt) break;
            r -= cnt; ++a;
        }
        int b = a;
        while (r >= NDIM - b) { r -= NDIM - b; ++b; }
        return (unsigned)a | ((unsigned)b << 7) | ((unsigned)(b + r) << 14);
    }
    return (unsigned)(33 + (c - 6545)) | (32u << 7) | (32u << 14);
}

// ---- 4-wide group table with fixup redirection, per phase ----
struct Tbl4 {
    unsigned e[4][TB_PAD];        // low16: byte off into s_all; [16..30): za byte off
    unsigned fixsrc[4][FIX_MAX];  // packed m3 factors for fixup slot
    int      ng[4];
    int      nfix[4];
};

static constexpr Tbl4 make_tbl4() {
    ColTbl ct = make_col_tbl();
    Tbl4 t{};
    for (int ph = 0; ph < 4; ++ph) {
        int ng = (NCOLS - ph) / 4;
        t.ng[ph] = ng;
        int nf = 0;
        for (int g = 0; g < ng; ++g) {
            int c0 = ph + 4 * g;
            unsigned k0 = ct.e[c0] & 1023u;
            unsigned a0 = (unsigned)(ct.e[c0] >> 10);
            bool uniform = true;
            for (int j = 1; j < 4; ++j) {
                unsigned kj = ct.e[c0 + j] & 1023u;
                unsigned aj = (unsigned)(ct.e[c0 + j] >> 10);
                if (kj != k0 + (unsigned)j || aj != a0) { uniform = false; break; }
            }
            if (uniform) {
                unsigned P   = (4u - (k0 & 3u)) & 3u;
                unsigned off = (P * SBUF_PAD + k0 + P) * 4u;
                t.e[ph][g] = off | ((a0 * 4u) << 16);
            } else {
                // redirect: 4 consecutive fixup floats (16B aligned), za = 1.0 (idx 32)
                unsigned off = (unsigned)(FIXBASE + nf) * 4u;
                t.e[ph][g] = off | ((32u * 4u) << 16);
                for (int j = 0; j < 4; ++j)
                    t.fixsrc[ph][nf++] = col_m3(c0 + j);
            }
        }
        t.nfix[ph] = nf;   // ~264 max, < FIX_MAX
        for (int g = ng; g < TB_PAD; ++g) t.e[ph][g] = 0;
        for (int i = nf; i < FIX_MAX; ++i) t.fixsrc[ph][i] = 32u | (32u << 7) | (32u << 14);
    }
    return t;
}
__device__ constexpr Tbl4 G4 = make_tbl4();

struct PairTbl { unsigned short e[NPAIRS]; };
static constexpr PairTbl make_pair_tbl() {
    PairTbl t{};
    int p = 0;
    for (int i = 0; i < NDIM; ++i)
        for (int j = i; j < NDIM; ++j)
            t.e[p++] = (unsigned short)((unsigned)i | ((unsigned)j << 8));
    return t;
}
__device__ constexpr PairTbl G_PAIR = make_pair_tbl();

__global__ __launch_bounds__(NTHREADS) void sindy_library_kernel(
    const float* __restrict__ z, float* __restrict__ out)
{
    // s_all: 4 shifted buf copies (copy P at P*SBUF_PAD; s_copyP[P+k] = buf[k]),
    // then the fixup region at FIXBASE. LDS.128 at (k0+P), P=(-k0)&3: 16B-aligned.
    __shared__ __align__(16) float s_all[SALL_N];
    __shared__ float s_mul[NDIM + 1];   // z..., 1.0f at [32]
    __shared__ float s_m3[65];          // z(32), 1.0 at [32], sin at [33..64]

    const int row = blockIdx.x;
    const int t   = threadIdx.x;

    if (t < NDIM) {
        float v  = z[row * NDIM + t];
        float sv = __sinf(v);
        s_mul[t]     = v;
        s_m3[t]      = v;
        s_m3[33 + t] = sv;
        #pragma unroll
        for (int P = 0; P < 4; ++P) {
            s_all[P * SBUF_PAD + P + 1 + t]   = v;
            s_all[P * SBUF_PAD + P + 561 + t] = sv;
        }
    } else if (t == NDIM) {
        s_mul[NDIM] = 1.0f;
        s_m3[32]    = 1.0f;
        #pragma unroll
        for (int P = 0; P < 4; ++P) s_all[P * SBUF_PAD + P] = 1.0f;
    }
    __syncthreads();

    const int ph = (4 - (row & 3)) & 3;

    // Pair products into all 4 shifted copies.
    for (int p = t; p < NPAIRS; p += NTHREADS) {
        unsigned ij = (unsigned)G_PAIR.e[p];
        float v = s_mul[ij & 31u] * s_mul[(ij >> 8) & 31u];
        #pragma unroll
        for (int P = 0; P < 4; ++P) s_all[P * SBUF_PAD + P + 33 + p] = v;
    }
    // Fixup values: pre-multiplied products of up to 3 factors (za folded in).
    {
        const int nfix = G4.nfix[ph];
        for (int f = t; f < nfix; f += NTHREADS) {
            unsigned s = __ldg(&G4.fixsrc[ph][f]);
            s_all[FIXBASE + f] =
                s_m3[s & 127u] * s_m3[(s >> 7) & 127u] * s_m3[(s >> 14) & 127u];
        }
    }
    __syncthreads();

    float* __restrict__ o = out + (size_t)row * NCOLS;

    // Head scalars (< 4 cols)
    if (t < ph) {
        unsigned e = (unsigned)G_COL.e[t];
        o[t] = s_mul[e >> 10] * s_all[e & 1023u];
    }

    const int ng = G4.ng[ph];
    const unsigned* __restrict__ tb = &G4.e[ph][0];
    const char* __restrict__ sc = (const char*)&s_all[0];
    const char* __restrict__ sm = (const char*)&s_mul[0];

    unsigned e = __ldg(&tb[t]);                   // prefetch first entry
    for (int g = t; g < ng; g += NTHREADS) {
        unsigned en = __ldg(&tb[g + NTHREADS]);   // padded: always in-bounds

        float4 b  = *(const float4*)(sc + (e & 0xFFFFu));
        float  za = *(const float*)(sm + (e >> 16));
        float4 r  = make_float4(za * b.x, za * b.y, za * b.z, za * b.w);

        __stcs((float4*)(o + ph + 4 * g), r);     // one 16B store per iter
        e = en;
    }

    // Tail scalars (< 4 cols)
    {
        int c = ph + 4 * ng + t;
        if (c < NCOLS) {
            unsigned ee = (unsigned)G_COL.e[c];
            o[c] = s_mul[ee >> 10] * s_all[ee & 1023u];
        }
    }
}

extern "C" void kernel_launch(void* const* d_in, const int* in_sizes, int n_in,
                              void* d_out, int out_size) {
    const float* z   = (const float*)d_in[0];
    float*       out = (float*)d_out;
    sindy_library_kernel<<<8192, NTHREADS>>>(z, out);
}